// round 3
// baseline (speedup 1.0000x reference)
#include <cuda_runtime.h>
#include <cstddef>

#define EPSBN 1e-5f

// Problem constants: b=4, c=64, h=256, w=512, kc=32
// Scratch layouts:
//   g_q, g_k : [b][w][h][32]
//   g_v, g_o : [b][w][h][64]
static __device__ float g_q[4 * 512 * 256 * 32];
static __device__ float g_k[4 * 512 * 256 * 32];
static __device__ float g_v[4 * 512 * 256 * 64];
static __device__ float g_o[4 * 512 * 256 * 64];

// ---------------- f32x2 helpers ----------------
__device__ __forceinline__ unsigned long long pack2(float lo, float hi) {
    unsigned long long r;
    asm("mov.b64 %0, {%1, %2};" : "=l"(r) : "f"(lo), "f"(hi));
    return r;
}
__device__ __forceinline__ float2 unpack2(unsigned long long v) {
    float2 r;
    asm("mov.b64 {%0, %1}, %2;" : "=f"(r.x), "=f"(r.y) : "l"(v));
    return r;
}
__device__ __forceinline__ void fma2(unsigned long long& acc,
                                     unsigned long long a,
                                     unsigned long long b) {
    asm("fma.rn.f32x2 %0, %1, %2, %0;" : "+l"(acc) : "l"(a), "l"(b));
}

// ---------------- Kernel 1: BN-folded projections as register-tiled GEMM --
// Out[128 rows][524288 pos] = A[128][64] * X[64][pos]
// Block: 256 threads = 8 warps. Tile: 128 rows x 128 positions.
// Warp rg (0..7) owns rows 16*rg .. 16*rg+15; lane owns 4 consecutive
// positions. Per c: 1 LDS.128 (x, conflict-free) + 4 LDS.128 (weights,
// broadcast) feed 32 FFMA2.
// Row map: rg0,1 -> q[0:16],q[16:32]; rg2,3 -> k; rg4..7 -> v.
__global__ void __launch_bounds__(256) proj_kernel(
    const float* __restrict__ x,
    const float* __restrict__ Wq, const float* __restrict__ qg,
    const float* __restrict__ qb, const float* __restrict__ qm,
    const float* __restrict__ qv,
    const float* __restrict__ Wk, const float* __restrict__ kg,
    const float* __restrict__ kb, const float* __restrict__ km,
    const float* __restrict__ kv,
    const float* __restrict__ Wv, const float* __restrict__ bvp)
{
    // dynamic smem: Ws2[64 c][64 rowpair] (32KB) | Xs[64 c][128 pos] (32KB)
    //               | bias2[64] (512B)
    extern __shared__ __align__(16) unsigned char dsm[];
    unsigned long long* Ws2 = (unsigned long long*)dsm;            // 4096 ull
    float* Xs = (float*)(dsm + 32768);                             // 8192 f
    unsigned long long* bias2 = (unsigned long long*)(dsm + 65536);

    const int tid = threadIdx.x;

    // ---- fold BN into weights/bias ----
    for (int idx = tid; idx < 4096; idx += 256) {
        const int rp = idx & 63;
        const int c  = idx >> 6;
        float a[2];
#pragma unroll
        for (int j = 0; j < 2; j++) {
            const int r = 2 * rp + j;
            float wgt;
            if (r < 32) {
                wgt = Wq[r * 64 + c] * (qg[r] * rsqrtf(qv[r] + EPSBN));
            } else if (r < 64) {
                const int rr = r - 32;
                wgt = Wk[rr * 64 + c] * (kg[rr] * rsqrtf(kv[rr] + EPSBN));
            } else {
                wgt = Wv[(r - 64) * 64 + c];
            }
            a[j] = wgt;
        }
        Ws2[c * 64 + rp] = pack2(a[0], a[1]);
    }
    if (tid < 64) {
        float bb[2];
#pragma unroll
        for (int j = 0; j < 2; j++) {
            const int r = 2 * tid + j;
            if (r < 32) {
                const float s = qg[r] * rsqrtf(qv[r] + EPSBN);
                bb[j] = qb[r] - qm[r] * s;
            } else if (r < 64) {
                const int rr = r - 32;
                const float s = kg[rr] * rsqrtf(kv[rr] + EPSBN);
                bb[j] = kb[rr] - km[rr] * s;
            } else {
                bb[j] = bvp[r - 64];
            }
        }
        bias2[tid] = pack2(bb[0], bb[1]);
    }

    // ---- stage x tile: 128 consecutive positions share (b,h) ----
    const int P0 = blockIdx.x * 128;
    const int b  = P0 >> 17;
    const int h  = (P0 & 131071) >> 9;
    const int w0 = P0 & 511;

    const float* xrow = x + (size_t)b * 8388608 + (size_t)h * 512 + w0;
#pragma unroll
    for (int i = 0; i < 8; i++) {
        const int idx = tid + i * 256;        // 0..2047 float4 slots
        const int c   = idx >> 5;
        const int c4  = idx & 31;
        float4 v4 = *(const float4*)(xrow + (size_t)c * 131072 + c4 * 4);
        *(float4*)(Xs + c * 128 + c4 * 4) = v4;
    }
    __syncthreads();

    const int rg   = tid >> 5;    // warp = row group
    const int lane = tid & 31;

    unsigned long long acc[32];   // [pair 0..7][pos 0..3]
#pragma unroll
    for (int pr = 0; pr < 8; pr++) {
        const unsigned long long bz = bias2[rg * 8 + pr];
#pragma unroll
        for (int p = 0; p < 4; p++) acc[pr * 4 + p] = bz;
    }

    const float* xsp = Xs + lane * 4;
    const ulonglong2* wsp = (const ulonglong2*)(Ws2 + rg * 8);

#pragma unroll 8
    for (int c = 0; c < 64; c++) {
        const float4 xv = *(const float4*)(xsp + c * 128);
        unsigned long long xx[4];
        xx[0] = pack2(xv.x, xv.x);
        xx[1] = pack2(xv.y, xv.y);
        xx[2] = pack2(xv.z, xv.z);
        xx[3] = pack2(xv.w, xv.w);
        const ulonglong2* wr = wsp + c * 32;   // 64 ull per c => 32 u2
#pragma unroll
        for (int i2 = 0; i2 < 4; i2++) {
            const ulonglong2 wp = wr[i2];
#pragma unroll
            for (int p = 0; p < 4; p++) {
                fma2(acc[(2 * i2) * 4 + p], wp.x, xx[p]);
                fma2(acc[(2 * i2 + 1) * 4 + p], wp.y, xx[p]);
            }
        }
    }

    // ---- write out: 16 consecutive floats per position ----
#pragma unroll
    for (int p = 0; p < 4; p++) {
        const int w = w0 + lane * 4 + p;
        const size_t bh = ((size_t)(b * 512 + w)) * 256 + h;
        float* dst;
        if (rg < 2)      dst = g_q + bh * 32 + (rg & 1) * 16;
        else if (rg < 4) dst = g_k + bh * 32 + (rg & 1) * 16;
        else             dst = g_v + bh * 64 + (rg - 4) * 16;
#pragma unroll
        for (int q4 = 0; q4 < 4; q4++) {
            float2 lo = unpack2(acc[(q4 * 2) * 4 + p]);
            float2 hi = unpack2(acc[(q4 * 2 + 1) * 4 + p]);
            *(float4*)(dst + q4 * 4) = make_float4(lo.x, lo.y, hi.x, hi.y);
        }
    }
}

// ---------------- Kernel 2: per-(b,w) vertical attention ----------------
// Block = one (b,w) column, 128 threads, 2 query rows per thread
// (h = tid and tid+128). K/V rows from smem amortized over both queries:
// 24 LDS.128 per 96 FFMA2. Streaming softmax without max subtraction.
__global__ void __launch_bounds__(128, 2) attn_kernel()
{
    extern __shared__ float smem[];
    float* Ks = smem;          // [256][32] = 32KB
    float* Vs = smem + 8192;   // [256][64] = 64KB

    const int tid = threadIdx.x;
    const int bw  = blockIdx.x;
    const size_t base32 = (size_t)bw * (256 * 32);
    const size_t base64 = (size_t)bw * (256 * 64);

    // Stage K and V (coalesced float4)
    {
        const float4* ksrc = (const float4*)(g_k + base32);
        float4* kdst = (float4*)Ks;
#pragma unroll
        for (int i = 0; i < 16; i++) kdst[tid + i * 128] = ksrc[tid + i * 128];
        const float4* vsrc = (const float4*)(g_v + base64);
        float4* vdst = (float4*)Vs;
#pragma unroll
        for (int i = 0; i < 32; i++) vdst[tid + i * 128] = vsrc[tid + i * 128];
    }
    __syncthreads();

    // Load the two query rows (contiguous 128B each)
    unsigned long long q0[16], q1[16];
    {
        const ulonglong2* s0 =
            (const ulonglong2*)(g_q + base32 + (size_t)tid * 32);
        const ulonglong2* s1 =
            (const ulonglong2*)(g_q + base32 + (size_t)(tid + 128) * 32);
#pragma unroll
        for (int i = 0; i < 8; i++) {
            ulonglong2 t0 = s0[i];
            q0[2 * i] = t0.x; q0[2 * i + 1] = t0.y;
            ulonglong2 t1 = s1[i];
            q1[2 * i] = t1.x; q1[2 * i + 1] = t1.y;
        }
    }

    unsigned long long acc0[32], acc1[32];
#pragma unroll
    for (int i = 0; i < 32; i++) { acc0[i] = 0ull; acc1[i] = 0ull; }
    float l0 = 0.0f, l1 = 0.0f;

#pragma unroll 1
    for (int g = 0; g < 256; g++) {
        const ulonglong2* krow = (const ulonglong2*)(Ks + g * 32);
        unsigned long long a0 = 0ull, b0 = 0ull, c0 = 0ull, d0 = 0ull;
        unsigned long long a1 = 0ull, b1 = 0ull, c1 = 0ull, d1 = 0ull;
#pragma unroll
        for (int i = 0; i < 2; i++) {
            ulonglong2 k0 = krow[4 * i + 0];
            ulonglong2 k1 = krow[4 * i + 1];
            ulonglong2 k2 = krow[4 * i + 2];
            ulonglong2 k3 = krow[4 * i + 3];
            fma2(a0, q0[8 * i + 0], k0.x);  fma2(a1, q1[8 * i + 0], k0.x);
            fma2(b0, q0[8 * i + 1], k0.y);  fma2(b1, q1[8 * i + 1], k0.y);
            fma2(c0, q0[8 * i + 2], k1.x);  fma2(c1, q1[8 * i + 2], k1.x);
            fma2(d0, q0[8 * i + 3], k1.y);  fma2(d1, q1[8 * i + 3], k1.y);
            fma2(a0, q0[8 * i + 4], k2.x);  fma2(a1, q1[8 * i + 4], k2.x);
            fma2(b0, q0[8 * i + 5], k2.y);  fma2(b1, q1[8 * i + 5], k2.y);
            fma2(c0, q0[8 * i + 6], k3.x);  fma2(c1, q1[8 * i + 6], k3.x);
            fma2(d0, q0[8 * i + 7], k3.y);  fma2(d1, q1[8 * i + 7], k3.y);
        }
        float2 fa = unpack2(a0), fb = unpack2(b0);
        float2 fc = unpack2(c0), fd = unpack2(d0);
        const float s0 = ((fa.x + fa.y) + (fb.x + fb.y)) +
                         ((fc.x + fc.y) + (fd.x + fd.y));
        fa = unpack2(a1); fb = unpack2(b1);
        fc = unpack2(c1); fd = unpack2(d1);
        const float s1 = ((fa.x + fa.y) + (fb.x + fb.y)) +
                         ((fc.x + fc.y) + (fd.x + fd.y));

        const float p0 = __expf(s0);
        const float p1 = __expf(s1);
        l0 += p0;
        l1 += p1;
        const unsigned long long pp0 = pack2(p0, p0);
        const unsigned long long pp1 = pack2(p1, p1);

        const ulonglong2* vrow = (const ulonglong2*)(Vs + g * 64);
#pragma unroll
        for (int i = 0; i < 16; i++) {
            ulonglong2 vv = vrow[i];
            fma2(acc0[2 * i],     pp0, vv.x);
            fma2(acc0[2 * i + 1], pp0, vv.y);
            fma2(acc1[2 * i],     pp1, vv.x);
            fma2(acc1[2 * i + 1], pp1, vv.y);
        }
    }

    const float inv0 = 1.0f / l0;
    const float inv1 = 1.0f / l1;
    float2* o0 = (float2*)(g_o + base64 + (size_t)tid * 64);
    float2* o1 = (float2*)(g_o + base64 + (size_t)(tid + 128) * 64);
#pragma unroll
    for (int i = 0; i < 32; i++) {
        float2 v0 = unpack2(acc0[i]);
        o0[i] = make_float2(v0.x * inv0, v0.y * inv0);
        float2 v1 = unpack2(acc1[i]);
        o1[i] = make_float2(v1.x * inv1, v1.y * inv1);
    }
}

// ---------------- Kernel 3: transpose + gamma*O + x ----------------
// out[b][d][h][w] = gamma * g_o[b][w][h][d] + x[b][d][h][w]
__global__ void __launch_bounds__(256) out_kernel(
    const float* __restrict__ x,
    const float* __restrict__ gammap,
    float* __restrict__ out)
{
    __shared__ float tile[32][33];

    const int tx = threadIdx.x;   // 0..31
    const int ty = threadIdx.y;   // 0..7
    const int wt = blockIdx.x & 15;
    const int dt = blockIdx.x >> 4;
    const int h  = blockIdx.y;
    const int b  = blockIdx.z;

    const float gamma = gammap[0];

#pragma unroll
    for (int j = 0; j < 4; j++) {
        const int w = wt * 32 + ty + j * 8;
        const int d = dt * 32 + tx;
        tile[ty + j * 8][tx] =
            g_o[((size_t)(b * 512 + w) * 256 + h) * 64 + d];
    }
    __syncthreads();

#pragma unroll
    for (int j = 0; j < 4; j++) {
        const int d = dt * 32 + ty + j * 8;
        const int w = wt * 32 + tx;
        const size_t oi = ((size_t)(b * 64 + d) * 256 + h) * 512 + w;
        out[oi] = gamma * tile[tx][ty + j * 8] + x[oi];
    }
}

// ---------------- launch ----------------
extern "C" void kernel_launch(void* const* d_in, const int* in_sizes, int n_in,
                              void* d_out, int out_size)
{
    const float* x    = (const float*)d_in[0];
    const float* Wq   = (const float*)d_in[1];
    const float* qg   = (const float*)d_in[2];
    const float* qb   = (const float*)d_in[3];
    const float* qm   = (const float*)d_in[4];
    const float* qvv  = (const float*)d_in[5];
    const float* Wk   = (const float*)d_in[6];
    const float* kg   = (const float*)d_in[7];
    const float* kb   = (const float*)d_in[8];
    const float* km   = (const float*)d_in[9];
    const float* kvv  = (const float*)d_in[10];
    const float* Wv   = (const float*)d_in[11];
    const float* bvp  = (const float*)d_in[12];
    const float* gam  = (const float*)d_in[13];
    float* out = (float*)d_out;

    cudaFuncSetAttribute(proj_kernel,
                         cudaFuncAttributeMaxDynamicSharedMemorySize, 66560);
    cudaFuncSetAttribute(attn_kernel,
                         cudaFuncAttributeMaxDynamicSharedMemorySize, 98304);

    proj_kernel<<<4096, 256, 66560>>>(x, Wq, qg, qb, qm, qvv,
                                      Wk, kg, kb, km, kvv, Wv, bvp);
    attn_kernel<<<2048, 128, 98304>>>();
    out_kernel<<<dim3(32, 256, 4), dim3(32, 8)>>>(x, gam, out);
}

// round 5
// speedup vs baseline: 1.7925x; 1.7925x over previous
#include <cuda_runtime.h>
#include <cuda_bf16.h>
#include <cstdint>
#include <cstddef>

#define EPSBN 1e-5f

// Problem constants: b=4, c=64, h=256, w=512, kc=32
// Scratch layouts:
//   g_q, g_k : [b][w][h][32] f32
//   g_v, g_o : [b][w][h][64] f32
static __device__ float g_q[4 * 512 * 256 * 32];
static __device__ float g_k[4 * 512 * 256 * 32];
static __device__ float g_v[4 * 512 * 256 * 64];
static __device__ float g_o[4 * 512 * 256 * 64];

// ==================== helpers ====================
__device__ __forceinline__ uint32_t smem_u32(const void* p) {
    uint32_t a;
    asm("{ .reg .u64 t; cvta.to.shared.u64 t, %1; cvt.u32.u64 %0, t; }"
        : "=r"(a) : "l"(p));
    return a;
}
#define SWZ(o) ((o) ^ (((o) >> 3) & 0x70))

#define LDSM_X4(r0, r1, r2, r3, a)                                         \
    asm volatile("ldmatrix.sync.aligned.m8n8.x4.shared.b16 "               \
                 "{%0, %1, %2, %3}, [%4];"                                 \
                 : "=r"(r0), "=r"(r1), "=r"(r2), "=r"(r3) : "r"(a) : "memory")
#define LDSM_X2(r0, r1, a)                                                 \
    asm volatile("ldmatrix.sync.aligned.m8n8.x2.shared.b16 "               \
                 "{%0, %1}, [%2];"                                         \
                 : "=r"(r0), "=r"(r1) : "r"(a) : "memory")

__device__ __forceinline__ void mma16816(float* d, const uint32_t* a,
                                         const uint32_t* b) {
    asm volatile(
        "mma.sync.aligned.m16n8k16.row.col.f32.bf16.bf16.f32 "
        "{%0, %1, %2, %3}, {%4, %5, %6, %7}, {%8, %9}, {%0, %1, %2, %3};"
        : "+f"(d[0]), "+f"(d[1]), "+f"(d[2]), "+f"(d[3])
        : "r"(a[0]), "r"(a[1]), "r"(a[2]), "r"(a[3]), "r"(b[0]), "r"(b[1]));
}

__device__ __forceinline__ uint32_t bf16pk(float a, float b) {
    uint32_t r;
    asm("cvt.rn.bf16x2.f32 %0, %1, %2;" : "=r"(r) : "f"(b), "f"(a));
    return r;   // a -> lower halfword (element 2k), b -> upper (2k+1)
}
__device__ __forceinline__ uint32_t hi_pair(float a, float b,
                                            float& ra, float& rb) {
    __nv_bfloat16 ha = __float2bfloat16_rn(a);
    __nv_bfloat16 hb = __float2bfloat16_rn(b);
    ra = a - __bfloat162float(ha);
    rb = b - __bfloat162float(hb);
    return ((uint32_t)__bfloat16_as_ushort(hb) << 16) |
           (uint32_t)__bfloat16_as_ushort(ha);
}

// f32x2 helpers (proj)
__device__ __forceinline__ unsigned long long pack2(float lo, float hi) {
    unsigned long long r;
    asm("mov.b64 %0, {%1, %2};" : "=l"(r) : "f"(lo), "f"(hi));
    return r;
}
__device__ __forceinline__ float2 unpack2(unsigned long long v) {
    float2 r;
    asm("mov.b64 {%0, %1}, %2;" : "=f"(r.x), "=f"(r.y) : "l"(v));
    return r;
}
__device__ __forceinline__ void fma2(unsigned long long& acc,
                                     unsigned long long a,
                                     unsigned long long b) {
    asm("fma.rn.f32x2 %0, %1, %2, %0;" : "+l"(acc) : "l"(a), "l"(b));
}

// ---------------- Kernel 1: BN-folded projections (unchanged) ------------
__global__ void __launch_bounds__(256) proj_kernel(
    const float* __restrict__ x,
    const float* __restrict__ Wq, const float* __restrict__ qg,
    const float* __restrict__ qb, const float* __restrict__ qm,
    const float* __restrict__ qv,
    const float* __restrict__ Wk, const float* __restrict__ kg,
    const float* __restrict__ kb, const float* __restrict__ km,
    const float* __restrict__ kv,
    const float* __restrict__ Wv, const float* __restrict__ bvp)
{
    extern __shared__ __align__(16) unsigned char dsm[];
    unsigned long long* Ws2 = (unsigned long long*)dsm;
    float* Xs = (float*)(dsm + 32768);
    unsigned long long* bias2 = (unsigned long long*)(dsm + 65536);

    const int tid = threadIdx.x;

    for (int idx = tid; idx < 4096; idx += 256) {
        const int rp = idx & 63;
        const int c  = idx >> 6;
        float a[2];
#pragma unroll
        for (int j = 0; j < 2; j++) {
            const int r = 2 * rp + j;
            float wgt;
            if (r < 32) {
                wgt = Wq[r * 64 + c] * (qg[r] * rsqrtf(qv[r] + EPSBN));
            } else if (r < 64) {
                const int rr = r - 32;
                wgt = Wk[rr * 64 + c] * (kg[rr] * rsqrtf(kv[rr] + EPSBN));
            } else {
                wgt = Wv[(r - 64) * 64 + c];
            }
            a[j] = wgt;
        }
        Ws2[c * 64 + rp] = pack2(a[0], a[1]);
    }
    if (tid < 64) {
        float bb[2];
#pragma unroll
        for (int j = 0; j < 2; j++) {
            const int r = 2 * tid + j;
            if (r < 32) {
                const float s = qg[r] * rsqrtf(qv[r] + EPSBN);
                bb[j] = qb[r] - qm[r] * s;
            } else if (r < 64) {
                const int rr = r - 32;
                const float s = kg[rr] * rsqrtf(kv[rr] + EPSBN);
                bb[j] = kb[rr] - km[rr] * s;
            } else {
                bb[j] = bvp[r - 64];
            }
        }
        bias2[tid] = pack2(bb[0], bb[1]);
    }

    const int P0 = blockIdx.x * 128;
    const int b  = P0 >> 17;
    const int h  = (P0 & 131071) >> 9;
    const int w0 = P0 & 511;

    const float* xrow = x + (size_t)b * 8388608 + (size_t)h * 512 + w0;
#pragma unroll
    for (int i = 0; i < 8; i++) {
        const int idx = tid + i * 256;
        const int c   = idx >> 5;
        const int c4  = idx & 31;
        float4 v4 = *(const float4*)(xrow + (size_t)c * 131072 + c4 * 4);
        *(float4*)(Xs + c * 128 + c4 * 4) = v4;
    }
    __syncthreads();

    const int rg   = tid >> 5;
    const int lane = tid & 31;

    unsigned long long acc[32];
#pragma unroll
    for (int pr = 0; pr < 8; pr++) {
        const unsigned long long bz = bias2[rg * 8 + pr];
#pragma unroll
        for (int p = 0; p < 4; p++) acc[pr * 4 + p] = bz;
    }

    const float* xsp = Xs + lane * 4;
    const ulonglong2* wsp = (const ulonglong2*)(Ws2 + rg * 8);

#pragma unroll 8
    for (int c = 0; c < 64; c++) {
        const float4 xv = *(const float4*)(xsp + c * 128);
        unsigned long long xx[4];
        xx[0] = pack2(xv.x, xv.x);
        xx[1] = pack2(xv.y, xv.y);
        xx[2] = pack2(xv.z, xv.z);
        xx[3] = pack2(xv.w, xv.w);
        const ulonglong2* wr = wsp + c * 32;
#pragma unroll
        for (int i2 = 0; i2 < 4; i2++) {
            const ulonglong2 wp = wr[i2];
#pragma unroll
            for (int p = 0; p < 4; p++) {
                fma2(acc[(2 * i2) * 4 + p], wp.x, xx[p]);
                fma2(acc[(2 * i2 + 1) * 4 + p], wp.y, xx[p]);
            }
        }
    }

#pragma unroll
    for (int p = 0; p < 4; p++) {
        const int w = w0 + lane * 4 + p;
        const size_t bh = ((size_t)(b * 512 + w)) * 256 + h;
        float* dst;
        if (rg < 2)      dst = g_q + bh * 32 + (rg & 1) * 16;
        else if (rg < 4) dst = g_k + bh * 32 + (rg & 1) * 16;
        else             dst = g_v + bh * 64 + (rg - 4) * 16;
#pragma unroll
        for (int q4 = 0; q4 < 4; q4++) {
            float2 lo = unpack2(acc[(q4 * 2) * 4 + p]);
            float2 hi = unpack2(acc[(q4 * 2 + 1) * 4 + p]);
            *(float4*)(dst + q4 * 4) = make_float4(lo.x, lo.y, hi.x, hi.y);
        }
    }
}

// ---------------- Kernel 2: mma.sync bf16 attention ----------------
// Block = one (b,w) column, 256 threads = 8 warps; warp owns 32 query rows.
// S = Qhi.Khi^T + Qhi.Klo^T + Qlo.Khi^T (fp32-accurate scores), P,V bf16.
// smem: Qs[256][64 bf16] (hi|lo) | Ks same | Vt[64][256 bf16] blocked atoms.
static constexpr int SM_Q = 0;
static constexpr int SM_K = 32768;
static constexpr int SM_V = 65536;
static constexpr int SM_TOT = 98304;

__device__ __forceinline__ uint32_t voff(int d, int g) {
    return (uint32_t)(((d >> 3) + (g >> 6) * 8) * 1024 +
                      (d & 7) * 128 + (g & 63) * 2);
}

__global__ void __launch_bounds__(256, 1) attn_kernel()
{
    extern __shared__ __align__(16) unsigned char sm[];
    const uint32_t sb = smem_u32(sm);
    const int tid  = threadIdx.x;
    const int lane = tid & 31;
    const int wid  = tid >> 5;
    const int bw   = blockIdx.x;
    const size_t base32 = (size_t)bw * 8192;
    const size_t base64 = (size_t)bw * 16384;

    // ---- stage Q and K as [row][hi32|lo32] bf16, SW128 128B rows ----
#pragma unroll
    for (int i = 0; i < 8; i++) {
        const int idx = tid + i * 256;          // 2048 float4 slots
        const int row = idx >> 3, q4 = idx & 7;
        {
            float4 v = *(const float4*)(g_q + base32 + (size_t)row * 32 + q4 * 4);
            float l0, l1, l2, l3;
            const uint32_t h01 = hi_pair(v.x, v.y, l0, l1);
            const uint32_t h23 = hi_pair(v.z, v.w, l2, l3);
            const uint32_t bo = row * 128 + q4 * 8;
            *(uint2*)(sm + SM_Q + SWZ(bo))      = make_uint2(h01, h23);
            *(uint2*)(sm + SM_Q + SWZ(bo + 64)) =
                make_uint2(bf16pk(l0, l1), bf16pk(l2, l3));
        }
        {
            float4 v = *(const float4*)(g_k + base32 + (size_t)row * 32 + q4 * 4);
            float l0, l1, l2, l3;
            const uint32_t h01 = hi_pair(v.x, v.y, l0, l1);
            const uint32_t h23 = hi_pair(v.z, v.w, l2, l3);
            const uint32_t bo = row * 128 + q4 * 8;
            *(uint2*)(sm + SM_K + SWZ(bo))      = make_uint2(h01, h23);
            *(uint2*)(sm + SM_K + SWZ(bo + 64)) =
                make_uint2(bf16pk(l0, l1), bf16pk(l2, l3));
        }
    }
    // ---- stage Vt[d][g] bf16, blocked atoms (8 d-rows x 64 g-cols) ----
#pragma unroll
    for (int i = 0; i < 8; i++) {
        const int it = tid + i * 256;           // 2048 = 128 g-pairs * 16 d4
        const int g2 = it >> 4;                 // g pair index (g = 2*g2)
        const int d4 = (it & 15) * 4;
        float4 va = *(const float4*)(g_v + base64 + (size_t)(2 * g2) * 64 + d4);
        float4 vb = *(const float4*)(g_v + base64 + (size_t)(2 * g2 + 1) * 64 + d4);
        const float fa[4] = {va.x, va.y, va.z, va.w};
        const float fb[4] = {vb.x, vb.y, vb.z, vb.w};
#pragma unroll
        for (int j = 0; j < 4; j++) {
            *(uint32_t*)(sm + SM_V + SWZ(voff(d4 + j, 2 * g2))) =
                bf16pk(fa[j], fb[j]);
        }
    }
    __syncthreads();

    const int m0 = wid * 32;
    const int lr = lane & 7;            // ldmatrix row within 8x8
    const int lm = (lane >> 3) & 1;     // matrix selector bit
    const int lq = lane >> 4;           // k-block selector for x4

    // ---- hoist Q A-frags: [mt][f: hi0,hi1,lo0,lo1][4] ----
    uint32_t aq[2][4][4];
#pragma unroll
    for (int mt = 0; mt < 2; mt++) {
#pragma unroll
        for (int f = 0; f < 4; f++) {
            const int row = m0 + mt * 16 + lm * 8 + lr;
            const int col = f * 16 + lq * 8;
            LDSM_X4(aq[mt][f][0], aq[mt][f][1], aq[mt][f][2], aq[mt][f][3],
                    sb + SM_Q + SWZ(row * 128 + col * 2));
        }
    }

    float oa[2][8][4];
#pragma unroll
    for (int mt = 0; mt < 2; mt++)
#pragma unroll
        for (int nt = 0; nt < 8; nt++)
#pragma unroll
            for (int j = 0; j < 4; j++) oa[mt][nt][j] = 0.0f;
    float ls[2][2] = {{0.0f, 0.0f}, {0.0f, 0.0f}};

#pragma unroll 1
    for (int ck = 0; ck < 4; ck++) {
        const int gc = ck * 64;

        // ---- S chunk [32 rows x 64 keys] ----
        float s[2][8][4];
#pragma unroll
        for (int mt = 0; mt < 2; mt++)
#pragma unroll
            for (int nt = 0; nt < 8; nt++)
#pragma unroll
                for (int j = 0; j < 4; j++) s[mt][nt][j] = 0.0f;

#pragma unroll
        for (int nt = 0; nt < 8; nt++) {
            const int g0 = gc + nt * 8;
            uint32_t bh0[2], bh1[2], bl0[2], bl1[2];
            const uint32_t krow = (uint32_t)(g0 + lr) * 128;
            LDSM_X2(bh0[0], bh0[1], sb + SM_K + SWZ(krow + (0  + lm * 8) * 2));
            LDSM_X2(bh1[0], bh1[1], sb + SM_K + SWZ(krow + (16 + lm * 8) * 2));
            LDSM_X2(bl0[0], bl0[1], sb + SM_K + SWZ(krow + (32 + lm * 8) * 2));
            LDSM_X2(bl1[0], bl1[1], sb + SM_K + SWZ(krow + (48 + lm * 8) * 2));
#pragma unroll
            for (int mt = 0; mt < 2; mt++) {
                mma16816(s[mt][nt], aq[mt][0], bh0);  // Qhi . Khi (k 0-15)
                mma16816(s[mt][nt], aq[mt][1], bh1);  // Qhi . Khi (k16-31)
                mma16816(s[mt][nt], aq[mt][0], bl0);  // Qhi . Klo
                mma16816(s[mt][nt], aq[mt][1], bl1);
                mma16816(s[mt][nt], aq[mt][2], bh0);  // Qlo . Khi
                mma16816(s[mt][nt], aq[mt][3], bh1);
            }
        }

        // ---- exp + row-sum partials ----
#pragma unroll
        for (int mt = 0; mt < 2; mt++) {
#pragma unroll
            for (int nt = 0; nt < 8; nt++) {
                const float e0 = __expf(s[mt][nt][0]);
                const float e1 = __expf(s[mt][nt][1]);
                const float e2 = __expf(s[mt][nt][2]);
                const float e3 = __expf(s[mt][nt][3]);
                s[mt][nt][0] = e0; s[mt][nt][1] = e1;
                s[mt][nt][2] = e2; s[mt][nt][3] = e3;
                ls[mt][0] += e0 + e1;
                ls[mt][1] += e2 + e3;
            }
        }

        // ---- repack accums -> P A-frags (in registers) ----
        uint32_t pa[2][4][4];
#pragma unroll
        for (int mt = 0; mt < 2; mt++) {
#pragma unroll
            for (int kt = 0; kt < 4; kt++) {
                pa[mt][kt][0] = bf16pk(s[mt][2 * kt][0],     s[mt][2 * kt][1]);
                pa[mt][kt][1] = bf16pk(s[mt][2 * kt][2],     s[mt][2 * kt][3]);
                pa[mt][kt][2] = bf16pk(s[mt][2 * kt + 1][0], s[mt][2 * kt + 1][1]);
                pa[mt][kt][3] = bf16pk(s[mt][2 * kt + 1][2], s[mt][2 * kt + 1][3]);
            }
        }

        // ---- O += P @ V ----
#pragma unroll
        for (int kt = 0; kt < 4; kt++) {
            const int g0 = gc + kt * 16;
#pragma unroll
            for (int nd = 0; nd < 8; nd++) {
                uint32_t bv[2];
                LDSM_X2(bv[0], bv[1],
                        sb + SM_V + SWZ(voff(nd * 8 + lr, g0 + lm * 8)));
                mma16816(oa[0][nd], pa[0][kt], bv);
                mma16816(oa[1][nd], pa[1][kt], bv);
            }
        }
    }

    // ---- reduce row sums across quad, scale, write ----
#pragma unroll
    for (int mt = 0; mt < 2; mt++) {
#pragma unroll
        for (int j = 0; j < 2; j++) {
            float l = ls[mt][j];
            l += __shfl_xor_sync(0xFFFFFFFF, l, 1);
            l += __shfl_xor_sync(0xFFFFFFFF, l, 2);
            ls[mt][j] = 1.0f / l;
        }
    }

#pragma unroll
    for (int mt = 0; mt < 2; mt++) {
        const int row0 = m0 + mt * 16 + (lane >> 2);
        const int dcol = 2 * (lane & 3);
        float* orow0 = g_o + base64 + (size_t)row0 * 64;
        float* orow1 = orow0 + 8 * 64;
#pragma unroll
        for (int nd = 0; nd < 8; nd++) {
            const int d = nd * 8 + dcol;
            *(float2*)(orow0 + d) = make_float2(oa[mt][nd][0] * ls[mt][0],
                                                oa[mt][nd][1] * ls[mt][0]);
            *(float2*)(orow1 + d) = make_float2(oa[mt][nd][2] * ls[mt][1],
                                                oa[mt][nd][3] * ls[mt][1]);
        }
    }
}

// ---------------- Kernel 3: transpose + gamma*O + x ----------------
__global__ void __launch_bounds__(256) out_kernel(
    const float* __restrict__ x,
    const float* __restrict__ gammap,
    float* __restrict__ out)
{
    __shared__ float tile[32][33];

    const int tx = threadIdx.x;
    const int ty = threadIdx.y;
    const int wt = blockIdx.x & 15;
    const int dt = blockIdx.x >> 4;
    const int h  = blockIdx.y;
    const int b  = blockIdx.z;

    const float gamma = gammap[0];

#pragma unroll
    for (int j = 0; j < 4; j++) {
        const int w = wt * 32 + ty + j * 8;
        const int d = dt * 32 + tx;
        tile[ty + j * 8][tx] =
            g_o[((size_t)(b * 512 + w) * 256 + h) * 64 + d];
    }
    __syncthreads();

#pragma unroll
    for (int j = 0; j < 4; j++) {
        const int d = dt * 32 + ty + j * 8;
        const int w = wt * 32 + tx;
        const size_t oi = ((size_t)(b * 64 + d) * 256 + h) * 512 + w;
        out[oi] = gamma * tile[tx][ty + j * 8] + x[oi];
    }
}

// ---------------- launch ----------------
extern "C" void kernel_launch(void* const* d_in, const int* in_sizes, int n_in,
                              void* d_out, int out_size)
{
    const float* x    = (const float*)d_in[0];
    const float* Wq   = (const float*)d_in[1];
    const float* qg   = (const float*)d_in[2];
    const float* qb   = (const float*)d_in[3];
    const float* qm   = (const float*)d_in[4];
    const float* qvv  = (const float*)d_in[5];
    const float* Wk   = (const float*)d_in[6];
    const float* kg   = (const float*)d_in[7];
    const float* kb   = (const float*)d_in[8];
    const float* km   = (const float*)d_in[9];
    const float* kvv  = (const float*)d_in[10];
    const float* Wv   = (const float*)d_in[11];
    const float* bvp  = (const float*)d_in[12];
    const float* gam  = (const float*)d_in[13];
    float* out = (float*)d_out;

    cudaFuncSetAttribute(proj_kernel,
                         cudaFuncAttributeMaxDynamicSharedMemorySize, 66560);
    cudaFuncSetAttribute(attn_kernel,
                         cudaFuncAttributeMaxDynamicSharedMemorySize, SM_TOT);

    proj_kernel<<<4096, 256, 66560>>>(x, Wq, qg, qb, qm, qvv,
                                      Wk, kg, kb, km, kvv, Wv, bvp);
    attn_kernel<<<2048, 256, SM_TOT>>>();
    out_kernel<<<dim3(32, 256, 4), dim3(32, 8)>>>(x, gam, out);
}

// round 6
// speedup vs baseline: 2.5831x; 1.4410x over previous
#include <cuda_runtime.h>
#include <cuda_bf16.h>
#include <cstdint>
#include <cstddef>

#define EPSBN 1e-5f

// Problem constants: b=4, c=64, h=256, w=512, kc=32
// Scratch layouts:
//   g_q, g_k : [b][w][h][32] f32
//   g_v, g_o : [b][w][h][64] f32
static __device__ float g_q[4 * 512 * 256 * 32];
static __device__ float g_k[4 * 512 * 256 * 32];
static __device__ float g_v[4 * 512 * 256 * 64];
static __device__ float g_o[4 * 512 * 256 * 64];

// ==================== helpers ====================
__device__ __forceinline__ uint32_t smem_u32(const void* p) {
    uint32_t a;
    asm("{ .reg .u64 t; cvta.to.shared.u64 t, %1; cvt.u32.u64 %0, t; }"
        : "=r"(a) : "l"(p));
    return a;
}
#define SWZ(o) ((o) ^ (((o) >> 3) & 0x70))

#define LDSM_X4(r0, r1, r2, r3, a)                                         \
    asm volatile("ldmatrix.sync.aligned.m8n8.x4.shared.b16 "               \
                 "{%0, %1, %2, %3}, [%4];"                                 \
                 : "=r"(r0), "=r"(r1), "=r"(r2), "=r"(r3) : "r"(a) : "memory")
#define LDSM_X4T(r0, r1, r2, r3, a)                                        \
    asm volatile("ldmatrix.sync.aligned.m8n8.x4.trans.shared.b16 "         \
                 "{%0, %1, %2, %3}, [%4];"                                 \
                 : "=r"(r0), "=r"(r1), "=r"(r2), "=r"(r3) : "r"(a) : "memory")
#define LDSM_X2(r0, r1, a)                                                 \
    asm volatile("ldmatrix.sync.aligned.m8n8.x2.shared.b16 "               \
                 "{%0, %1}, [%2];"                                         \
                 : "=r"(r0), "=r"(r1) : "r"(a) : "memory")

__device__ __forceinline__ void mma16816(float* d, const uint32_t* a,
                                         const uint32_t* b) {
    asm volatile(
        "mma.sync.aligned.m16n8k16.row.col.f32.bf16.bf16.f32 "
        "{%0, %1, %2, %3}, {%4, %5, %6, %7}, {%8, %9}, {%0, %1, %2, %3};"
        : "+f"(d[0]), "+f"(d[1]), "+f"(d[2]), "+f"(d[3])
        : "r"(a[0]), "r"(a[1]), "r"(a[2]), "r"(a[3]), "r"(b[0]), "r"(b[1]));
}

__device__ __forceinline__ uint32_t bf16pk(float a, float b) {
    uint32_t r;
    asm("cvt.rn.bf16x2.f32 %0, %1, %2;" : "=r"(r) : "f"(b), "f"(a));
    return r;   // a -> lower halfword (element 2k), b -> upper (2k+1)
}
__device__ __forceinline__ uint32_t hi_pair(float a, float b,
                                            float& ra, float& rb) {
    __nv_bfloat16 ha = __float2bfloat16_rn(a);
    __nv_bfloat16 hb = __float2bfloat16_rn(b);
    ra = a - __bfloat162float(ha);
    rb = b - __bfloat162float(hb);
    return ((uint32_t)__bfloat16_as_ushort(hb) << 16) |
           (uint32_t)__bfloat16_as_ushort(ha);
}

// ---------------- Kernel 1: tensor-core BN-folded projections -------------
// Out[pos][128 ch] = X[pos][64 c] * Wfold^T + bias, computed as
// 3 bf16 products (XhiWhi + XhiWlo + XloWhi) on mma.sync.m16n8k16.
// Block: 256 thr = 8 warps, tile 64 pos x 128 ch. Warp = 16 pos x 64 ch.
// X staged [c][pos] (natural coalesced layout), A-frags via ldmatrix.trans.
// W staged [ch][c] rows (B operand, same pattern as attn's K).
static constexpr int PJ_WHI  = 0;        // [128 ch][64 c] bf16, 16KB
static constexpr int PJ_WLO  = 16384;
static constexpr int PJ_XHI  = 32768;    // [64 c][64 pos] bf16, 8KB
static constexpr int PJ_XLO  = 40960;
static constexpr int PJ_BIAS = 49152;    // 128 f32
static constexpr int PJ_TOT  = 49664;

__global__ void __launch_bounds__(256) proj_kernel(
    const float* __restrict__ x,
    const float* __restrict__ Wq, const float* __restrict__ qg,
    const float* __restrict__ qb, const float* __restrict__ qm,
    const float* __restrict__ qv,
    const float* __restrict__ Wk, const float* __restrict__ kg,
    const float* __restrict__ kb, const float* __restrict__ km,
    const float* __restrict__ kv,
    const float* __restrict__ Wv, const float* __restrict__ bvp)
{
    extern __shared__ __align__(16) unsigned char psm[];
    const uint32_t sb = smem_u32(psm);
    const int tid  = threadIdx.x;
    const int lane = tid & 31;
    const int wid  = tid >> 5;

    // ---- fold BN into W, split hi/lo bf16, store [ch][c] SW128 rows ----
    for (int idx = tid; idx < 4096; idx += 256) {
        const int ch = idx >> 5;
        const int c2 = (idx & 31) * 2;
        float w0, w1;
        if (ch < 32) {
            const float s = qg[ch] * rsqrtf(qv[ch] + EPSBN);
            w0 = Wq[ch * 64 + c2] * s;
            w1 = Wq[ch * 64 + c2 + 1] * s;
        } else if (ch < 64) {
            const int r = ch - 32;
            const float s = kg[r] * rsqrtf(kv[r] + EPSBN);
            w0 = Wk[r * 64 + c2] * s;
            w1 = Wk[r * 64 + c2 + 1] * s;
        } else {
            w0 = Wv[(ch - 64) * 64 + c2];
            w1 = Wv[(ch - 64) * 64 + c2 + 1];
        }
        float l0, l1;
        const uint32_t hi = hi_pair(w0, w1, l0, l1);
        const uint32_t off = SWZ((uint32_t)(ch * 128 + c2 * 2));
        *(uint32_t*)(psm + PJ_WHI + off) = hi;
        *(uint32_t*)(psm + PJ_WLO + off) = bf16pk(l0, l1);
    }
    if (tid < 128) {
        float bb;
        if (tid < 32) {
            const float s = qg[tid] * rsqrtf(qv[tid] + EPSBN);
            bb = qb[tid] - qm[tid] * s;
        } else if (tid < 64) {
            const int r = tid - 32;
            const float s = kg[r] * rsqrtf(kv[r] + EPSBN);
            bb = kb[r] - km[r] * s;
        } else {
            bb = bvp[tid - 64];
        }
        ((float*)(psm + PJ_BIAS))[tid] = bb;
    }

    // ---- stage x tile [64 c][64 pos] hi/lo bf16 (coalesced read) ----
    const int P0  = blockIdx.x * 64;
    const int b   = P0 >> 17;
    const int h   = (P0 & 131071) >> 9;
    const int w0p = P0 & 511;
    const float* xrow = x + (size_t)b * 8388608 + (size_t)h * 512 + w0p;
#pragma unroll
    for (int i = 0; i < 4; i++) {
        const int idx = tid + i * 256;          // 1024 float4 slots
        const int c = idx >> 4, p4 = (idx & 15) * 4;
        float4 v = *(const float4*)(xrow + (size_t)c * 131072 + p4);
        float l0, l1, l2, l3;
        const uint32_t h01 = hi_pair(v.x, v.y, l0, l1);
        const uint32_t h23 = hi_pair(v.z, v.w, l2, l3);
        const uint32_t off = SWZ((uint32_t)(c * 128 + p4 * 2));
        *(uint2*)(psm + PJ_XHI + off) = make_uint2(h01, h23);
        *(uint2*)(psm + PJ_XLO + off) =
            make_uint2(bf16pk(l0, l1), bf16pk(l2, l3));
    }
    __syncthreads();

    const int pw   = wid & 3;            // pos group (16 pos each)
    const int cw   = wid >> 2;           // ch half (64 ch each)
    const int pos0 = pw * 16;
    const int lr   = lane & 7;
    const int lm   = (lane >> 3) & 1;
    const int cEx  = (lane >> 4) * 8;          // k-block for A trans frags
    const int pEx  = ((lane >> 3) & 1) * 8;    // m-block for A trans frags

    // ---- A frags (X) via ldmatrix.trans: rows=pos, cols=c ----
    uint32_t axh[4][4], axl[4][4];
#pragma unroll
    for (int kk = 0; kk < 4; kk++) {
        const uint32_t a =
            SWZ((uint32_t)((kk * 16 + cEx + lr) * 128 + (pos0 + pEx) * 2));
        LDSM_X4T(axh[kk][0], axh[kk][1], axh[kk][2], axh[kk][3],
                 sb + PJ_XHI + a);
        LDSM_X4T(axl[kk][0], axl[kk][1], axl[kk][2], axl[kk][3],
                 sb + PJ_XLO + a);
    }

    // ---- accumulators init = bias ----
    const float* bias = (const float*)(psm + PJ_BIAS);
    float d[8][4];
#pragma unroll
    for (int nt = 0; nt < 8; nt++) {
        const int ch = cw * 64 + nt * 8 + 2 * (lane & 3);
        const float b0 = bias[ch], b1 = bias[ch + 1];
        d[nt][0] = b0; d[nt][1] = b1; d[nt][2] = b0; d[nt][3] = b1;
    }

    // ---- GEMM: 8 n-tiles x 4 k-steps x 3 products ----
#pragma unroll
    for (int nt = 0; nt < 8; nt++) {
        const uint32_t wr = (uint32_t)((cw * 64 + nt * 8 + lr) * 128);
#pragma unroll
        for (int kk = 0; kk < 4; kk++) {
            uint32_t bh[2], bl[2];
            const uint32_t cb = SWZ(wr + (kk * 16 + lm * 8) * 2);
            LDSM_X2(bh[0], bh[1], sb + PJ_WHI + cb);
            LDSM_X2(bl[0], bl[1], sb + PJ_WLO + cb);
            mma16816(d[nt], axh[kk], bh);
            mma16816(d[nt], axh[kk], bl);
            mma16816(d[nt], axl[kk], bh);
        }
    }

    // ---- write: D frag rows = pos, cols = ch ----
    const int wv = w0p + pos0 + (lane >> 2);
    const size_t r0 = ((size_t)(b * 512 + wv) * 256 + h);
    const size_t r1 = ((size_t)(b * 512 + wv + 8) * 256 + h);
#pragma unroll
    for (int nt = 0; nt < 8; nt++) {
        const int ch = cw * 64 + nt * 8 + 2 * (lane & 3);
        float *p0, *p1;
        if (ch < 32) {
            p0 = g_q + r0 * 32 + ch;        p1 = g_q + r1 * 32 + ch;
        } else if (ch < 64) {
            p0 = g_k + r0 * 32 + (ch - 32); p1 = g_k + r1 * 32 + (ch - 32);
        } else {
            p0 = g_v + r0 * 64 + (ch - 64); p1 = g_v + r1 * 64 + (ch - 64);
        }
        *(float2*)p0 = make_float2(d[nt][0], d[nt][1]);
        *(float2*)p1 = make_float2(d[nt][2], d[nt][3]);
    }
}

// ---------------- Kernel 2: mma.sync bf16 attention (unchanged) ----------
static constexpr int SM_Q = 0;
static constexpr int SM_K = 32768;
static constexpr int SM_V = 65536;
static constexpr int SM_TOT = 98304;

__device__ __forceinline__ uint32_t voff(int d, int g) {
    return (uint32_t)(((d >> 3) + (g >> 6) * 8) * 1024 +
                      (d & 7) * 128 + (g & 63) * 2);
}

__global__ void __launch_bounds__(256, 1) attn_kernel()
{
    extern __shared__ __align__(16) unsigned char sm[];
    const uint32_t sb = smem_u32(sm);
    const int tid  = threadIdx.x;
    const int lane = tid & 31;
    const int wid  = tid >> 5;
    const int bw   = blockIdx.x;
    const size_t base32 = (size_t)bw * 8192;
    const size_t base64 = (size_t)bw * 16384;

#pragma unroll
    for (int i = 0; i < 8; i++) {
        const int idx = tid + i * 256;
        const int row = idx >> 3, q4 = idx & 7;
        {
            float4 v = *(const float4*)(g_q + base32 + (size_t)row * 32 + q4 * 4);
            float l0, l1, l2, l3;
            const uint32_t h01 = hi_pair(v.x, v.y, l0, l1);
            const uint32_t h23 = hi_pair(v.z, v.w, l2, l3);
            const uint32_t bo = row * 128 + q4 * 8;
            *(uint2*)(sm + SM_Q + SWZ(bo))      = make_uint2(h01, h23);
            *(uint2*)(sm + SM_Q + SWZ(bo + 64)) =
                make_uint2(bf16pk(l0, l1), bf16pk(l2, l3));
        }
        {
            float4 v = *(const float4*)(g_k + base32 + (size_t)row * 32 + q4 * 4);
            float l0, l1, l2, l3;
            const uint32_t h01 = hi_pair(v.x, v.y, l0, l1);
            const uint32_t h23 = hi_pair(v.z, v.w, l2, l3);
            const uint32_t bo = row * 128 + q4 * 8;
            *(uint2*)(sm + SM_K + SWZ(bo))      = make_uint2(h01, h23);
            *(uint2*)(sm + SM_K + SWZ(bo + 64)) =
                make_uint2(bf16pk(l0, l1), bf16pk(l2, l3));
        }
    }
#pragma unroll
    for (int i = 0; i < 8; i++) {
        const int it = tid + i * 256;
        const int g2 = it >> 4;
        const int d4 = (it & 15) * 4;
        float4 va = *(const float4*)(g_v + base64 + (size_t)(2 * g2) * 64 + d4);
        float4 vb = *(const float4*)(g_v + base64 + (size_t)(2 * g2 + 1) * 64 + d4);
        const float fa[4] = {va.x, va.y, va.z, va.w};
        const float fb[4] = {vb.x, vb.y, vb.z, vb.w};
#pragma unroll
        for (int j = 0; j < 4; j++) {
            *(uint32_t*)(sm + SM_V + SWZ(voff(d4 + j, 2 * g2))) =
                bf16pk(fa[j], fb[j]);
        }
    }
    __syncthreads();

    const int m0 = wid * 32;
    const int lr = lane & 7;
    const int lm = (lane >> 3) & 1;
    const int lq = lane >> 4;

    uint32_t aq[2][4][4];
#pragma unroll
    for (int mt = 0; mt < 2; mt++) {
#pragma unroll
        for (int f = 0; f < 4; f++) {
            const int row = m0 + mt * 16 + lm * 8 + lr;
            const int col = f * 16 + lq * 8;
            LDSM_X4(aq[mt][f][0], aq[mt][f][1], aq[mt][f][2], aq[mt][f][3],
                    sb + SM_Q + SWZ(row * 128 + col * 2));
        }
    }

    float oa[2][8][4];
#pragma unroll
    for (int mt = 0; mt < 2; mt++)
#pragma unroll
        for (int nt = 0; nt < 8; nt++)
#pragma unroll
            for (int j = 0; j < 4; j++) oa[mt][nt][j] = 0.0f;
    float ls[2][2] = {{0.0f, 0.0f}, {0.0f, 0.0f}};

#pragma unroll 1
    for (int ck = 0; ck < 4; ck++) {
        const int gc = ck * 64;

        float s[2][8][4];
#pragma unroll
        for (int mt = 0; mt < 2; mt++)
#pragma unroll
            for (int nt = 0; nt < 8; nt++)
#pragma unroll
                for (int j = 0; j < 4; j++) s[mt][nt][j] = 0.0f;

#pragma unroll
        for (int nt = 0; nt < 8; nt++) {
            const int g0 = gc + nt * 8;
            uint32_t bh0[2], bh1[2], bl0[2], bl1[2];
            const uint32_t krow = (uint32_t)(g0 + lr) * 128;
            LDSM_X2(bh0[0], bh0[1], sb + SM_K + SWZ(krow + (0  + lm * 8) * 2));
            LDSM_X2(bh1[0], bh1[1], sb + SM_K + SWZ(krow + (16 + lm * 8) * 2));
            LDSM_X2(bl0[0], bl0[1], sb + SM_K + SWZ(krow + (32 + lm * 8) * 2));
            LDSM_X2(bl1[0], bl1[1], sb + SM_K + SWZ(krow + (48 + lm * 8) * 2));
#pragma unroll
            for (int mt = 0; mt < 2; mt++) {
                mma16816(s[mt][nt], aq[mt][0], bh0);
                mma16816(s[mt][nt], aq[mt][1], bh1);
                mma16816(s[mt][nt], aq[mt][0], bl0);
                mma16816(s[mt][nt], aq[mt][1], bl1);
                mma16816(s[mt][nt], aq[mt][2], bh0);
                mma16816(s[mt][nt], aq[mt][3], bh1);
            }
        }

#pragma unroll
        for (int mt = 0; mt < 2; mt++) {
#pragma unroll
            for (int nt = 0; nt < 8; nt++) {
                const float e0 = __expf(s[mt][nt][0]);
                const float e1 = __expf(s[mt][nt][1]);
                const float e2 = __expf(s[mt][nt][2]);
                const float e3 = __expf(s[mt][nt][3]);
                s[mt][nt][0] = e0; s[mt][nt][1] = e1;
                s[mt][nt][2] = e2; s[mt][nt][3] = e3;
                ls[mt][0] += e0 + e1;
                ls[mt][1] += e2 + e3;
            }
        }

        uint32_t pa[2][4][4];
#pragma unroll
        for (int mt = 0; mt < 2; mt++) {
#pragma unroll
            for (int kt = 0; kt < 4; kt++) {
                pa[mt][kt][0] = bf16pk(s[mt][2 * kt][0],     s[mt][2 * kt][1]);
                pa[mt][kt][1] = bf16pk(s[mt][2 * kt][2],     s[mt][2 * kt][3]);
                pa[mt][kt][2] = bf16pk(s[mt][2 * kt + 1][0], s[mt][2 * kt + 1][1]);
                pa[mt][kt][3] = bf16pk(s[mt][2 * kt + 1][2], s[mt][2 * kt + 1][3]);
            }
        }

#pragma unroll
        for (int kt = 0; kt < 4; kt++) {
            const int g0 = gc + kt * 16;
#pragma unroll
            for (int nd = 0; nd < 8; nd++) {
                uint32_t bv[2];
                LDSM_X2(bv[0], bv[1],
                        sb + SM_V + SWZ(voff(nd * 8 + lr, g0 + lm * 8)));
                mma16816(oa[0][nd], pa[0][kt], bv);
                mma16816(oa[1][nd], pa[1][kt], bv);
            }
        }
    }

#pragma unroll
    for (int mt = 0; mt < 2; mt++) {
#pragma unroll
        for (int j = 0; j < 2; j++) {
            float l = ls[mt][j];
            l += __shfl_xor_sync(0xFFFFFFFF, l, 1);
            l += __shfl_xor_sync(0xFFFFFFFF, l, 2);
            ls[mt][j] = 1.0f / l;
        }
    }

#pragma unroll
    for (int mt = 0; mt < 2; mt++) {
        const int row0 = m0 + mt * 16 + (lane >> 2);
        const int dcol = 2 * (lane & 3);
        float* orow0 = g_o + base64 + (size_t)row0 * 64;
        float* orow1 = orow0 + 8 * 64;
#pragma unroll
        for (int nd = 0; nd < 8; nd++) {
            const int d = nd * 8 + dcol;
            *(float2*)(orow0 + d) = make_float2(oa[mt][nd][0] * ls[mt][0],
                                                oa[mt][nd][1] * ls[mt][0]);
            *(float2*)(orow1 + d) = make_float2(oa[mt][nd][2] * ls[mt][1],
                                                oa[mt][nd][3] * ls[mt][1]);
        }
    }
}

// ---------------- Kernel 3: transpose + gamma*O + x ----------------
__global__ void __launch_bounds__(256) out_kernel(
    const float* __restrict__ x,
    const float* __restrict__ gammap,
    float* __restrict__ out)
{
    __shared__ float tile[32][33];

    const int tx = threadIdx.x;
    const int ty = threadIdx.y;
    const int wt = blockIdx.x & 15;
    const int dt = blockIdx.x >> 4;
    const int h  = blockIdx.y;
    const int b  = blockIdx.z;

    const float gamma = gammap[0];

#pragma unroll
    for (int j = 0; j < 4; j++) {
        const int w = wt * 32 + ty + j * 8;
        const int d = dt * 32 + tx;
        tile[ty + j * 8][tx] =
            g_o[((size_t)(b * 512 + w) * 256 + h) * 64 + d];
    }
    __syncthreads();

#pragma unroll
    for (int j = 0; j < 4; j++) {
        const int d = dt * 32 + ty + j * 8;
        const int w = wt * 32 + tx;
        const size_t oi = ((size_t)(b * 64 + d) * 256 + h) * 512 + w;
        out[oi] = gamma * tile[tx][ty + j * 8] + x[oi];
    }
}

// ---------------- launch ----------------
extern "C" void kernel_launch(void* const* d_in, const int* in_sizes, int n_in,
                              void* d_out, int out_size)
{
    const float* x    = (const float*)d_in[0];
    const float* Wq   = (const float*)d_in[1];
    const float* qg   = (const float*)d_in[2];
    const float* qb   = (const float*)d_in[3];
    const float* qm   = (const float*)d_in[4];
    const float* qvv  = (const float*)d_in[5];
    const float* Wk   = (const float*)d_in[6];
    const float* kg   = (const float*)d_in[7];
    const float* kb   = (const float*)d_in[8];
    const float* km   = (const float*)d_in[9];
    const float* kvv  = (const float*)d_in[10];
    const float* Wv   = (const float*)d_in[11];
    const float* bvp  = (const float*)d_in[12];
    const float* gam  = (const float*)d_in[13];
    float* out = (float*)d_out;

    cudaFuncSetAttribute(proj_kernel,
                         cudaFuncAttributeMaxDynamicSharedMemorySize, PJ_TOT);
    cudaFuncSetAttribute(attn_kernel,
                         cudaFuncAttributeMaxDynamicSharedMemorySize, SM_TOT);

    proj_kernel<<<8192, 256, PJ_TOT>>>(x, Wq, qg, qb, qm, qvv,
                                       Wk, kg, kb, km, kvv, Wv, bvp);
    attn_kernel<<<2048, 256, SM_TOT>>>();
    out_kernel<<<dim3(32, 256, 4), dim3(32, 8)>>>(x, gam, out);
}

// round 7
// speedup vs baseline: 2.6544x; 1.0276x over previous
#include <cuda_runtime.h>
#include <cuda_bf16.h>
#include <cstdint>
#include <cstddef>

#define EPSBN 1e-5f

// Problem constants: b=4, c=64, h=256, w=512, kc=32
// Scratch (bf16 era):
//   g_q, g_k : [b][w][h] rows of 128B = 32 ch as bf16 hi(words 0-15)|lo(16-31)
//   g_v      : [b][w][h] rows of 128B = 64 ch bf16
//   g_o      : [b][w][h] rows of 128B = 64 ch bf16
static __device__ __align__(16) uint32_t g_q[4 * 512 * 256 * 32];
static __device__ __align__(16) uint32_t g_k[4 * 512 * 256 * 32];
static __device__ __align__(16) uint32_t g_v[4 * 512 * 256 * 32];
static __device__ __align__(16) uint32_t g_o[4 * 512 * 256 * 32];

// ==================== helpers ====================
__device__ __forceinline__ uint32_t smem_u32(const void* p) {
    uint32_t a;
    asm("{ .reg .u64 t; cvta.to.shared.u64 t, %1; cvt.u32.u64 %0, t; }"
        : "=r"(a) : "l"(p));
    return a;
}
#define SWZ(o) ((o) ^ (((o) >> 3) & 0x70))

#define LDSM_X4(r0, r1, r2, r3, a)                                         \
    asm volatile("ldmatrix.sync.aligned.m8n8.x4.shared.b16 "               \
                 "{%0, %1, %2, %3}, [%4];"                                 \
                 : "=r"(r0), "=r"(r1), "=r"(r2), "=r"(r3) : "r"(a) : "memory")
#define LDSM_X4T(r0, r1, r2, r3, a)                                        \
    asm volatile("ldmatrix.sync.aligned.m8n8.x4.trans.shared.b16 "         \
                 "{%0, %1, %2, %3}, [%4];"                                 \
                 : "=r"(r0), "=r"(r1), "=r"(r2), "=r"(r3) : "r"(a) : "memory")
#define LDSM_X2(r0, r1, a)                                                 \
    asm volatile("ldmatrix.sync.aligned.m8n8.x2.shared.b16 "               \
                 "{%0, %1}, [%2];"                                         \
                 : "=r"(r0), "=r"(r1) : "r"(a) : "memory")

__device__ __forceinline__ void mma16816(float* d, const uint32_t* a,
                                         const uint32_t* b) {
    asm volatile(
        "mma.sync.aligned.m16n8k16.row.col.f32.bf16.bf16.f32 "
        "{%0, %1, %2, %3}, {%4, %5, %6, %7}, {%8, %9}, {%0, %1, %2, %3};"
        : "+f"(d[0]), "+f"(d[1]), "+f"(d[2]), "+f"(d[3])
        : "r"(a[0]), "r"(a[1]), "r"(a[2]), "r"(a[3]), "r"(b[0]), "r"(b[1]));
}

__device__ __forceinline__ uint32_t bf16pk(float a, float b) {
    uint32_t r;
    asm("cvt.rn.bf16x2.f32 %0, %1, %2;" : "=r"(r) : "f"(b), "f"(a));
    return r;   // a -> lower halfword, b -> upper
}
__device__ __forceinline__ uint32_t hi_pair(float a, float b,
                                            float& ra, float& rb) {
    __nv_bfloat16 ha = __float2bfloat16_rn(a);
    __nv_bfloat16 hb = __float2bfloat16_rn(b);
    ra = a - __bfloat162float(ha);
    rb = b - __bfloat162float(hb);
    return ((uint32_t)__bfloat16_as_ushort(hb) << 16) |
           (uint32_t)__bfloat16_as_ushort(ha);
}

// ---------------- Kernel 1: tensor-core BN-folded projections -------------
// Same GEMM as Round 6; outputs written in consumer-ready bf16 formats.
static constexpr int PJ_WHI  = 0;        // [128 ch][64 c] bf16, 16KB
static constexpr int PJ_WLO  = 16384;
static constexpr int PJ_XHI  = 32768;    // [64 c][64 pos] bf16, 8KB
static constexpr int PJ_XLO  = 40960;
static constexpr int PJ_BIAS = 49152;    // 128 f32
static constexpr int PJ_TOT  = 49664;

__global__ void __launch_bounds__(256) proj_kernel(
    const float* __restrict__ x,
    const float* __restrict__ Wq, const float* __restrict__ qg,
    const float* __restrict__ qb, const float* __restrict__ qm,
    const float* __restrict__ qv,
    const float* __restrict__ Wk, const float* __restrict__ kg,
    const float* __restrict__ kb, const float* __restrict__ km,
    const float* __restrict__ kv,
    const float* __restrict__ Wv, const float* __restrict__ bvp)
{
    extern __shared__ __align__(16) unsigned char psm[];
    const uint32_t sb = smem_u32(psm);
    const int tid  = threadIdx.x;
    const int lane = tid & 31;
    const int wid  = tid >> 5;

    // ---- fold BN into W, split hi/lo bf16, store [ch][c] SW128 rows ----
    for (int idx = tid; idx < 4096; idx += 256) {
        const int ch = idx >> 5;
        const int c2 = (idx & 31) * 2;
        float w0, w1;
        if (ch < 32) {
            const float s = qg[ch] * rsqrtf(qv[ch] + EPSBN);
            w0 = Wq[ch * 64 + c2] * s;
            w1 = Wq[ch * 64 + c2 + 1] * s;
        } else if (ch < 64) {
            const int r = ch - 32;
            const float s = kg[r] * rsqrtf(kv[r] + EPSBN);
            w0 = Wk[r * 64 + c2] * s;
            w1 = Wk[r * 64 + c2 + 1] * s;
        } else {
            w0 = Wv[(ch - 64) * 64 + c2];
            w1 = Wv[(ch - 64) * 64 + c2 + 1];
        }
        float l0, l1;
        const uint32_t hi = hi_pair(w0, w1, l0, l1);
        const uint32_t off = SWZ((uint32_t)(ch * 128 + c2 * 2));
        *(uint32_t*)(psm + PJ_WHI + off) = hi;
        *(uint32_t*)(psm + PJ_WLO + off) = bf16pk(l0, l1);
    }
    if (tid < 128) {
        float bb;
        if (tid < 32) {
            const float s = qg[tid] * rsqrtf(qv[tid] + EPSBN);
            bb = qb[tid] - qm[tid] * s;
        } else if (tid < 64) {
            const int r = tid - 32;
            const float s = kg[r] * rsqrtf(kv[r] + EPSBN);
            bb = kb[r] - km[r] * s;
        } else {
            bb = bvp[tid - 64];
        }
        ((float*)(psm + PJ_BIAS))[tid] = bb;
    }

    // ---- stage x tile [64 c][64 pos] hi/lo bf16 (coalesced read) ----
    const int P0  = blockIdx.x * 64;
    const int b   = P0 >> 17;
    const int h   = (P0 & 131071) >> 9;
    const int w0p = P0 & 511;
    const float* xrow = x + (size_t)b * 8388608 + (size_t)h * 512 + w0p;
#pragma unroll
    for (int i = 0; i < 4; i++) {
        const int idx = tid + i * 256;
        const int c = idx >> 4, p4 = (idx & 15) * 4;
        float4 v = *(const float4*)(xrow + (size_t)c * 131072 + p4);
        float l0, l1, l2, l3;
        const uint32_t h01 = hi_pair(v.x, v.y, l0, l1);
        const uint32_t h23 = hi_pair(v.z, v.w, l2, l3);
        const uint32_t off = SWZ((uint32_t)(c * 128 + p4 * 2));
        *(uint2*)(psm + PJ_XHI + off) = make_uint2(h01, h23);
        *(uint2*)(psm + PJ_XLO + off) =
            make_uint2(bf16pk(l0, l1), bf16pk(l2, l3));
    }
    __syncthreads();

    const int pw   = wid & 3;
    const int cw   = wid >> 2;
    const int pos0 = pw * 16;
    const int lr   = lane & 7;
    const int lm   = (lane >> 3) & 1;
    const int cEx  = (lane >> 4) * 8;
    const int pEx  = ((lane >> 3) & 1) * 8;

    uint32_t axh[4][4], axl[4][4];
#pragma unroll
    for (int kk = 0; kk < 4; kk++) {
        const uint32_t a =
            SWZ((uint32_t)((kk * 16 + cEx + lr) * 128 + (pos0 + pEx) * 2));
        LDSM_X4T(axh[kk][0], axh[kk][1], axh[kk][2], axh[kk][3],
                 sb + PJ_XHI + a);
        LDSM_X4T(axl[kk][0], axl[kk][1], axl[kk][2], axl[kk][3],
                 sb + PJ_XLO + a);
    }

    const float* bias = (const float*)(psm + PJ_BIAS);
    float d[8][4];
#pragma unroll
    for (int nt = 0; nt < 8; nt++) {
        const int ch = cw * 64 + nt * 8 + 2 * (lane & 3);
        const float b0 = bias[ch], b1 = bias[ch + 1];
        d[nt][0] = b0; d[nt][1] = b1; d[nt][2] = b0; d[nt][3] = b1;
    }

#pragma unroll
    for (int nt = 0; nt < 8; nt++) {
        const uint32_t wr = (uint32_t)((cw * 64 + nt * 8 + lr) * 128);
#pragma unroll
        for (int kk = 0; kk < 4; kk++) {
            uint32_t bh[2], bl[2];
            const uint32_t cb = SWZ(wr + (kk * 16 + lm * 8) * 2);
            LDSM_X2(bh[0], bh[1], sb + PJ_WHI + cb);
            LDSM_X2(bl[0], bl[1], sb + PJ_WLO + cb);
            mma16816(d[nt], axh[kk], bh);
            mma16816(d[nt], axh[kk], bl);
            mma16816(d[nt], axl[kk], bh);
        }
    }

    // ---- write bf16 formats: q/k hi|lo rows, v plain bf16 ----
    const int wv = w0p + pos0 + (lane >> 2);
    const size_t r0 = ((size_t)(b * 512 + wv) * 256 + h);
    const size_t r1 = ((size_t)(b * 512 + wv + 8) * 256 + h);
#pragma unroll
    for (int nt = 0; nt < 8; nt++) {
        const int ch = cw * 64 + nt * 8 + 2 * (lane & 3);
        if (ch < 64) {
            uint32_t* gq = (ch < 32) ? g_q : g_k;
            const int p = (ch & 31) >> 1;
            float l0, l1;
            uint32_t hi = hi_pair(d[nt][0], d[nt][1], l0, l1);
            gq[r0 * 32 + p]      = hi;
            gq[r0 * 32 + 16 + p] = bf16pk(l0, l1);
            hi = hi_pair(d[nt][2], d[nt][3], l0, l1);
            gq[r1 * 32 + p]      = hi;
            gq[r1 * 32 + 16 + p] = bf16pk(l0, l1);
        } else {
            const int p = (ch - 64) >> 1;
            g_v[r0 * 32 + p] = bf16pk(d[nt][0], d[nt][1]);
            g_v[r1 * 32 + p] = bf16pk(d[nt][2], d[nt][3]);
        }
    }
}

// ---------------- Kernel 2: mma.sync bf16 attention ----------------
static constexpr int SM_Q = 0;
static constexpr int SM_K = 32768;
static constexpr int SM_V = 65536;
static constexpr int SM_TOT = 98304;

__device__ __forceinline__ uint32_t voff(int d, int g) {
    return (uint32_t)(((d >> 3) + (g >> 6) * 8) * 1024 +
                      (d & 7) * 128 + (g & 63) * 2);
}

__global__ void __launch_bounds__(256, 1) attn_kernel()
{
    extern __shared__ __align__(16) unsigned char sm[];
    const uint32_t sb = smem_u32(sm);
    const int tid  = threadIdx.x;
    const int lane = tid & 31;
    const int wid  = tid >> 5;
    const int bw   = blockIdx.x;
    const size_t rowbase = (size_t)bw * 256;      // first row of this column

    // ---- stage Q and K: pure swizzled uint4 copies (already hi|lo bf16) ----
    {
        const uint4* qsrc = (const uint4*)g_q + rowbase * 8;
        const uint4* ksrc = (const uint4*)g_k + rowbase * 8;
#pragma unroll
        for (int i = 0; i < 8; i++) {
            const int idx = tid + i * 256;        // 2048 uint4 slots
            const int row = idx >> 3, q4 = idx & 7;
            const uint32_t dst = SWZ((uint32_t)(row * 128 + q4 * 16));
            *(uint4*)(sm + SM_Q + dst) = qsrc[idx];
            *(uint4*)(sm + SM_K + dst) = ksrc[idx];
        }
    }
    // ---- stage Vt[d][g]: transpose bf16 pairs via byte_perm ----
    {
        const uint4* vsrc = (const uint4*)g_v + rowbase * 8;
#pragma unroll
        for (int i = 0; i < 4; i++) {
            const int idx = tid + i * 256;        // 1024 slots: g-pair x d8
            const int g2 = idx >> 3, d8 = idx & 7;
            const uint4 va = vsrc[(2 * g2) * 8 + d8];
            const uint4 vb = vsrc[(2 * g2 + 1) * 8 + d8];
            const uint32_t aw[4] = {va.x, va.y, va.z, va.w};
            const uint32_t bwd[4] = {vb.x, vb.y, vb.z, vb.w};
#pragma unroll
            for (int j = 0; j < 4; j++) {
                const int ch = d8 * 8 + 2 * j;
                *(uint32_t*)(sm + SM_V + SWZ(voff(ch, 2 * g2))) =
                    __byte_perm(aw[j], bwd[j], 0x5410);
                *(uint32_t*)(sm + SM_V + SWZ(voff(ch + 1, 2 * g2))) =
                    __byte_perm(aw[j], bwd[j], 0x7632);
            }
        }
    }
    __syncthreads();

    const int m0 = wid * 32;
    const int lr = lane & 7;
    const int lm = (lane >> 3) & 1;
    const int lq = lane >> 4;

    uint32_t aq[2][4][4];
#pragma unroll
    for (int mt = 0; mt < 2; mt++) {
#pragma unroll
        for (int f = 0; f < 4; f++) {
            const int row = m0 + mt * 16 + lm * 8 + lr;
            const int col = f * 16 + lq * 8;
            LDSM_X4(aq[mt][f][0], aq[mt][f][1], aq[mt][f][2], aq[mt][f][3],
                    sb + SM_Q + SWZ(row * 128 + col * 2));
        }
    }

    float oa[2][8][4];
#pragma unroll
    for (int mt = 0; mt < 2; mt++)
#pragma unroll
        for (int nt = 0; nt < 8; nt++)
#pragma unroll
            for (int j = 0; j < 4; j++) oa[mt][nt][j] = 0.0f;
    float ls[2][2] = {{0.0f, 0.0f}, {0.0f, 0.0f}};

#pragma unroll 1
    for (int ck = 0; ck < 4; ck++) {
        const int gc = ck * 64;

        float s[2][8][4];
#pragma unroll
        for (int mt = 0; mt < 2; mt++)
#pragma unroll
            for (int nt = 0; nt < 8; nt++)
#pragma unroll
                for (int j = 0; j < 4; j++) s[mt][nt][j] = 0.0f;

#pragma unroll
        for (int nt = 0; nt < 8; nt++) {
            const int g0 = gc + nt * 8;
            uint32_t bh0[2], bh1[2], bl0[2], bl1[2];
            const uint32_t krow = (uint32_t)(g0 + lr) * 128;
            LDSM_X2(bh0[0], bh0[1], sb + SM_K + SWZ(krow + (0  + lm * 8) * 2));
            LDSM_X2(bh1[0], bh1[1], sb + SM_K + SWZ(krow + (16 + lm * 8) * 2));
            LDSM_X2(bl0[0], bl0[1], sb + SM_K + SWZ(krow + (32 + lm * 8) * 2));
            LDSM_X2(bl1[0], bl1[1], sb + SM_K + SWZ(krow + (48 + lm * 8) * 2));
#pragma unroll
            for (int mt = 0; mt < 2; mt++) {
                mma16816(s[mt][nt], aq[mt][0], bh0);
                mma16816(s[mt][nt], aq[mt][1], bh1);
                mma16816(s[mt][nt], aq[mt][0], bl0);
                mma16816(s[mt][nt], aq[mt][1], bl1);
                mma16816(s[mt][nt], aq[mt][2], bh0);
                mma16816(s[mt][nt], aq[mt][3], bh1);
            }
        }

#pragma unroll
        for (int mt = 0; mt < 2; mt++) {
#pragma unroll
            for (int nt = 0; nt < 8; nt++) {
                const float e0 = __expf(s[mt][nt][0]);
                const float e1 = __expf(s[mt][nt][1]);
                const float e2 = __expf(s[mt][nt][2]);
                const float e3 = __expf(s[mt][nt][3]);
                s[mt][nt][0] = e0; s[mt][nt][1] = e1;
                s[mt][nt][2] = e2; s[mt][nt][3] = e3;
                ls[mt][0] += e0 + e1;
                ls[mt][1] += e2 + e3;
            }
        }

        uint32_t pa[2][4][4];
#pragma unroll
        for (int mt = 0; mt < 2; mt++) {
#pragma unroll
            for (int kt = 0; kt < 4; kt++) {
                pa[mt][kt][0] = bf16pk(s[mt][2 * kt][0],     s[mt][2 * kt][1]);
                pa[mt][kt][1] = bf16pk(s[mt][2 * kt][2],     s[mt][2 * kt][3]);
                pa[mt][kt][2] = bf16pk(s[mt][2 * kt + 1][0], s[mt][2 * kt + 1][1]);
                pa[mt][kt][3] = bf16pk(s[mt][2 * kt + 1][2], s[mt][2 * kt + 1][3]);
            }
        }

#pragma unroll
        for (int kt = 0; kt < 4; kt++) {
            const int g0 = gc + kt * 16;
#pragma unroll
            for (int nd = 0; nd < 8; nd++) {
                uint32_t bv[2];
                LDSM_X2(bv[0], bv[1],
                        sb + SM_V + SWZ(voff(nd * 8 + lr, g0 + lm * 8)));
                mma16816(oa[0][nd], pa[0][kt], bv);
                mma16816(oa[1][nd], pa[1][kt], bv);
            }
        }
    }

#pragma unroll
    for (int mt = 0; mt < 2; mt++) {
#pragma unroll
        for (int j = 0; j < 2; j++) {
            float l = ls[mt][j];
            l += __shfl_xor_sync(0xFFFFFFFF, l, 1);
            l += __shfl_xor_sync(0xFFFFFFFF, l, 2);
            ls[mt][j] = 1.0f / l;
        }
    }

    // ---- write O as bf16 pairs ----
#pragma unroll
    for (int mt = 0; mt < 2; mt++) {
        const int row0 = m0 + mt * 16 + (lane >> 2);
        uint32_t* o0 = g_o + (rowbase + row0) * 32;
        uint32_t* o1 = o0 + 8 * 32;
#pragma unroll
        for (int nd = 0; nd < 8; nd++) {
            const int p = nd * 4 + (lane & 3);
            o0[p] = bf16pk(oa[mt][nd][0] * ls[mt][0],
                           oa[mt][nd][1] * ls[mt][0]);
            o1[p] = bf16pk(oa[mt][nd][2] * ls[mt][1],
                           oa[mt][nd][3] * ls[mt][1]);
        }
    }
}

// ---------------- Kernel 3: transpose + gamma*O + x ----------------
// out[b][d][h][w] = gamma * o[b][w][h][d] + x[b][d][h][w], o in bf16
__global__ void __launch_bounds__(256) out_kernel(
    const float* __restrict__ x,
    const float* __restrict__ gammap,
    float* __restrict__ out)
{
    __shared__ float tile[32][33];

    const int tx = threadIdx.x;   // 0..31
    const int ty = threadIdx.y;   // 0..7
    const int tid = ty * 32 + tx;
    const int wt = blockIdx.x & 15;
    const int dt = blockIdx.x >> 4;
    const int h  = blockIdx.y;
    const int b  = blockIdx.z;

    const float gamma = gammap[0];

    // load o tile: uint32 = 2 adjacent d per thread, coalesced along d
#pragma unroll
    for (int i = 0; i < 2; i++) {
        const int idx = tid + i * 256;        // 512 words = 32 w x 16 dw
        const int w  = idx >> 4;
        const int dw = idx & 15;
        const uint32_t wv =
            g_o[((size_t)(b * 512 + wt * 32 + w) * 256 + h) * 32 + dt * 16 + dw];
        const __nv_bfloat162 b2 = *(const __nv_bfloat162*)&wv;
        const float2 f2 = __bfloat1622float2(b2);
        tile[w][dw * 2]     = f2.x;
        tile[w][dw * 2 + 1] = f2.y;
    }
    __syncthreads();

#pragma unroll
    for (int j = 0; j < 4; j++) {
        const int d = dt * 32 + ty + j * 8;
        const int w = wt * 32 + tx;
        const size_t oi = ((size_t)(b * 64 + d) * 256 + h) * 512 + w;
        out[oi] = gamma * tile[tx][ty + j * 8] + x[oi];
    }
}

// ---------------- launch ----------------
extern "C" void kernel_launch(void* const* d_in, const int* in_sizes, int n_in,
                              void* d_out, int out_size)
{
    const float* x    = (const float*)d_in[0];
    const float* Wq   = (const float*)d_in[1];
    const float* qg   = (const float*)d_in[2];
    const float* qb   = (const float*)d_in[3];
    const float* qm   = (const float*)d_in[4];
    const float* qvv  = (const float*)d_in[5];
    const float* Wk   = (const float*)d_in[6];
    const float* kg   = (const float*)d_in[7];
    const float* kb   = (const float*)d_in[8];
    const float* km   = (const float*)d_in[9];
    const float* kvv  = (const float*)d_in[10];
    const float* Wv   = (const float*)d_in[11];
    const float* bvp  = (const float*)d_in[12];
    const float* gam  = (const float*)d_in[13];
    float* out = (float*)d_out;

    cudaFuncSetAttribute(proj_kernel,
                         cudaFuncAttributeMaxDynamicSharedMemorySize, PJ_TOT);
    cudaFuncSetAttribute(attn_kernel,
                         cudaFuncAttributeMaxDynamicSharedMemorySize, SM_TOT);

    proj_kernel<<<8192, 256, PJ_TOT>>>(x, Wq, qg, qb, qm, qvv,
                                       Wk, kg, kb, km, kvv, Wv, bvp);
    attn_kernel<<<2048, 256, SM_TOT>>>();
    out_kernel<<<dim3(32, 256, 4), dim3(32, 8)>>>(x, gam, out);
}